// round 13
// baseline (speedup 1.0000x reference)
#include <cuda_runtime.h>
#include <math.h>

// ---------------- problem constants ----------------
#define BG   256
#define NPG  256
#define NN   (BG*NPG)            // 65536 nodes
#define EE   (NN*16)             // 1048576 edges
#define KK   25
#define F1   32
#define F2   64
#define F3   128
#define NC1  (BG*64)             // 16384 pool-1 clusters
#define NC2  (BG*16)             // 4096  pool-2 clusters
#define NBCAP 64                 // max in-edges per node (avg 16)

// ---------------- device scratch (zero-init consistent; state restored per replay) ----
__device__ float    d_m[4];
__device__ int      d_ncnt1[NN];
__device__ unsigned char d_nbuf[(size_t)NN*NBCAP];   // 4MB: per-node source bytes
__device__ float    d_x2[NC1*F1];
__device__ float    d_cnt1[NC1];
__device__ float    d_pos2[NC1*2];
__device__ int      d_bcnt2[NC1];
__device__ unsigned char d_bkt2[NC1*64];
__device__ int      d_bcnt3[NC2];
__device__ unsigned char d_bkt3[NC2*16];
__device__ float    d_acc2[(size_t)NC1*KK*F1];  // pre-divided by deg
__device__ unsigned d_x3u[NC2*F2];              // monotone-uint max buffer (0 = -NaN sentinel)
__device__ float    d_x3f[NC2*F2];              // decoded floats
__device__ float    d_cnt2[NC2];
__device__ float    d_pos3[NC2*2];
__device__ float    d_acc3[(size_t)NC2*KK*F2];  // pre-divided by deg
__device__ float    d_h3[NC2*F3];

// ---------------- helpers ----------------
__device__ __forceinline__ float eluf(float v){ return v > 0.f ? v : expm1f(v); }

// monotone float<->uint (0u == -NaN == below all reals)
__device__ __forceinline__ unsigned fenc(float v){
    unsigned b = __float_as_uint(v);
    return (b & 0x80000000u) ? ~b : (b | 0x80000000u);
}
__device__ __forceinline__ float fdec(unsigned u){
    unsigned b = (u & 0x80000000u) ? (u ^ 0x80000000u) : ~u;
    return __uint_as_float(b);
}

__device__ __forceinline__ void atomicMaxF(float* a, float v){
    if (v >= 0.f) atomicMax((int*)a, __float_as_int(v));
    else          atomicMin((unsigned int*)a, __float_as_uint(v));
}

__device__ __forceinline__ void warpMaxAtomic(float mx, float* dst){
    #pragma unroll
    for (int o = 16; o; o >>= 1) mx = fmaxf(mx, __shfl_xor_sync(0xffffffffu, mx, o));
    if ((threadIdx.x & 31) == 0) atomicMax((int*)dst, __float_as_int(mx));
}

__device__ __forceinline__ void spline_corners(float psx, float psy,
                                               int& ix, int& iy, float& fx, float& fy){
    float vx = psx * 4.f, vy = psy * 4.f;
    float fix = fminf(fmaxf(floorf(vx), 0.f), 3.f);
    float fiy = fminf(fmaxf(floorf(vy), 0.f), 3.f);
    fx = vx - fix; fy = vy - fiy;
    ix = (int)fix; iy = (int)fiy;
}

__device__ __forceinline__ int cell1(float px, float py){
    int cx = min(max((int)floorf(px * 0.25f), 0), 7);
    int cy = min(max((int)floorf(py * 0.25f), 0), 7);
    return cx * 8 + cy;
}
__device__ __forceinline__ int clu2_of(int j){
    float px = d_pos2[2*j], py = d_pos2[2*j+1];
    int cx = min(max((int)floorf(px * 0.125f), 0), 3);
    int cy = min(max((int)floorf(py * 0.125f), 0), 3);
    return (j >> 6) * 16 + cx * 4 + cy;
}

// f32x2 packed FMA helpers
__device__ __forceinline__ unsigned long long splat2(float x){
    unsigned long long r;
    asm("mov.b64 %0, {%1, %1};" : "=l"(r) : "f"(x));
    return r;
}
__device__ __forceinline__ void ffma2(unsigned long long& d,
                                      unsigned long long a, unsigned long long b){
    asm("fma.rn.f32x2 %0, %1, %2, %0;" : "+l"(d) : "l"(a), "l"(b));
}
__device__ __forceinline__ float f2lo(unsigned long long u){ return __uint_as_float((unsigned)u); }
__device__ __forceinline__ float f2hi(unsigned long long u){ return __uint_as_float((unsigned)(u>>32)); }

// bucket edges by target node (4 edges per thread)
__global__ void k_nbucket(const int4* __restrict__ row4, const int4* __restrict__ col4){
    int i = blockIdx.x*blockDim.x + threadIdx.x;     // EE/4 threads
    int4 r = row4[i], c = col4[i];
    int s0 = atomicAdd(&d_ncnt1[r.x], 1);
    if (s0 < NBCAP) d_nbuf[(size_t)r.x*NBCAP + s0] = (unsigned char)(c.x & 255);
    int s1 = atomicAdd(&d_ncnt1[r.y], 1);
    if (s1 < NBCAP) d_nbuf[(size_t)r.y*NBCAP + s1] = (unsigned char)(c.y & 255);
    int s2 = atomicAdd(&d_ncnt1[r.z], 1);
    if (s2 < NBCAP) d_nbuf[(size_t)r.z*NBCAP + s2] = (unsigned char)(c.z & 255);
    int s3 = atomicAdd(&d_ncnt1[r.w], 1);
    if (s3 < NBCAP) d_nbuf[(size_t)r.w*NBCAP + s3] = (unsigned char)(c.w & 255);
}

// global pseudo max (level 1); block per graph
__global__ void k_m1g(const float* __restrict__ pos){
    __shared__ float2 ps[NPG];
    int g = blockIdx.x, t = threadIdx.x;
    ps[t] = ((const float2*)pos)[g*NPG + t];
    __syncthreads();
    int gn = g*NPG + t;
    int cnt = min(d_ncnt1[gn], NBCAP);
    const unsigned char* nb = d_nbuf + (size_t)gn*NBCAP;
    float2 mp = ps[t];
    float mx = 0.f;
    for (int e = 0; e < cnt; e++){
        float2 pc = ps[nb[e]];
        mx = fmaxf(mx, fmaxf(fabsf(pc.x - mp.x), fabsf(pc.y - mp.y)));
    }
    warpMaxAtomic(mx, &d_m[0]);
}

// ---------------- mega-kernel: layer1 conv+pool + level2/3 graph build (512 thr) ----------------
__global__ void __launch_bounds__(512) k_graph1(
        const float* __restrict__ x, const float* __restrict__ pos,
        const float* __restrict__ W1, const float* __restrict__ r1,
        const float* __restrict__ b1){
    extern __shared__ float acc_dyn[];     // 512*26 floats = 53.2KB
    __shared__ float  x2_s[64*F1];         // 8KB
    __shared__ unsigned char bkt_s[64*64]; // 4KB
    __shared__ float  W1s[KK*F1];          // 3.2KB
    __shared__ float2 ps[NPG];             // 2KB
    __shared__ float  xs_s[NPG];           // 1KB
    __shared__ unsigned char cell_s[NPG];
    __shared__ unsigned bm_s[128];
    __shared__ int    bcnt_s[64];
    __shared__ float  cnt1_s[64];
    __shared__ float  pos2_s[64*2];
    __shared__ unsigned char cell2_s[64];
    __shared__ unsigned bm3_s[8];
    __shared__ int    bcnt3_s[16];
    __shared__ unsigned char bkt3_s[16*16];
    __shared__ float  cnt2_s[16];
    __shared__ float  pos3_s[16*2];
    __shared__ float  r1s[F1], b1s[F1];

    int g = blockIdx.x, t = threadIdx.x;   // 512 threads
    int half = t >> 8;                      // 0/1
    int n = t & 255;                        // node within graph
    int gn = g*NPG + n;

    // ---- P1: loads + zeroing ----
    float2 myp = ((const float2*)pos)[gn];
    if (half == 0){
        ps[n] = myp;
        xs_s[n] = x[gn];
        cell_s[n] = (unsigned char)cell1(myp.x, myp.y);
    }
    for (int i = t; i < KK*F1; i += 512) W1s[i] = W1[i];
    if (t < F1){ r1s[t] = r1[t]; b1s[t] = b1[t]; }
    #pragma unroll
    for (int k = 0; k < 26; k++) acc_dyn[t*26 + k] = 0.f;
    {
        const float NEG = -3.4e38f;
        for (int i = t; i < 64*F1; i += 512) x2_s[i] = NEG;
    }
    if (t < 128) bm_s[t] = 0u;
    if (t < 64){ bcnt_s[t] = 0; cnt1_s[t] = 0.f; pos2_s[2*t] = 0.f; pos2_s[2*t+1] = 0.f; }
    if (t < 16){ bcnt3_s[t] = 0; cnt2_s[t] = 0.f; pos3_s[2*t] = 0.f; pos3_s[2*t+1] = 0.f; }
    if (t < 8) bm3_s[t] = 0u;
    __syncthreads();

    // ---- P2: per-node edge accumulation (split across thread pair) + level-2 dedup ----
    int rawcnt = d_ncnt1[gn];
    int cnt = min(rawcnt, NBCAP);
    const unsigned char* nb = d_nbuf + (size_t)gn*NBCAP;
    float inv1 = 1.f / (2.f * d_m[0] + 1e-12f);
    float* ar = &acc_dyn[t*26];
    int r2cell = cell_s[n];
    for (int e = half; e < cnt; e += 2){
        int c = nb[e];
        float2 pc = ps[c];
        float psx = (pc.x - myp.x) * inv1 + 0.5f;
        float psy = (pc.y - myp.y) * inv1 + 0.5f;
        int ix, iy; float fx, fy;
        spline_corners(psx, psy, ix, iy, fx, fy);
        float xin = xs_s[c];
        int kb = ix*5 + iy;
        float w00 = (1.f-fx)*(1.f-fy), w01 = (1.f-fx)*fy;
        float w10 = fx*(1.f-fy),       w11 = fx*fy;
        ar[kb  ] += w00 * xin;
        ar[kb+1] += w01 * xin;
        ar[kb+5] += w10 * xin;
        ar[kb+6] += w11 * xin;
        int c2 = cell_s[c];
        if (r2cell != c2){
            int key = r2cell*64 + c2;
            unsigned bit = 1u << (key & 31);
            unsigned old = atomicOr(&bm_s[key >> 5], bit);
            if (!(old & bit)){
                int sl = atomicAdd(&bcnt_s[r2cell], 1);
                bkt_s[r2cell*64 + sl] = (unsigned char)c2;
            }
        }
    }
    // restore ncnt1 = 0 for next replay (all reads done)
    if (half == 0) d_ncnt1[gn] = 0;
    __syncthreads();
    // merge the two half-accumulators into rows [0,256)
    if (half == 0){
        #pragma unroll
        for (int k = 0; k < 25; k++) ar[k] += acc_dyn[(t+256)*26 + k];
    }
    __syncthreads();

    // ---- P3: node transform (each thread computes 16 of 32 outputs) + pool-1 ----
    {
        float invd = 1.f / fmaxf((float)rawcnt, 1.f);
        float xn = xs_s[n];
        const float* arn = &acc_dyn[n*26];
        int ob = half*16;
        float h[16];
        #pragma unroll
        for (int j = 0; j < 16; j++) h[j] = b1s[ob+j] + xn * r1s[ob+j];
        #pragma unroll
        for (int k = 0; k < KK; k++){
            float a = arn[k] * invd;
            #pragma unroll
            for (int j = 0; j < 16; j++) h[j] += a * W1s[k*F1 + ob + j];
        }
        int cl = r2cell;
        if (half == 0){
            atomicAdd(&cnt1_s[cl], 1.f);
            atomicAdd(&pos2_s[2*cl],   myp.x);
            atomicAdd(&pos2_s[2*cl+1], myp.y);
        }
        #pragma unroll
        for (int j = 0; j < 16; j++)
            atomicMaxF(&x2_s[cl*F1 + ob + j], eluf(h[j]));
    }
    __syncthreads();

    // ---- P4: finalize clusters ----
    if (t < 64){
        float c = cnt1_s[t];
        float invc = 1.f / fmaxf(c, 1.f);
        float px = pos2_s[2*t] * invc, py = pos2_s[2*t+1] * invc;
        pos2_s[2*t] = px; pos2_s[2*t+1] = py;
        int cx = min(max((int)floorf(px * 0.125f), 0), 3);
        int cy = min(max((int)floorf(py * 0.125f), 0), 3);
        cell2_s[t] = (unsigned char)(cx*4 + cy);
        d_cnt1[g*64 + t] = c;
        d_pos2[(g*64 + t)*2]     = px;
        d_pos2[(g*64 + t)*2 + 1] = py;
        d_bcnt2[g*64 + t] = bcnt_s[t];
    }
    __syncthreads();

    // ---- P5: write x2 (zero empty clusters) + pool-2 meta ----
    for (int i = t; i < 64*F1; i += 512){
        int cl = i >> 5;
        d_x2[g*64*F1 + i] = (cnt1_s[cl] > 0.f) ? x2_s[i] : 0.f;
    }
    if (t < 64 && cnt1_s[t] > 0.f){
        int c2 = cell2_s[t];
        atomicAdd(&cnt2_s[c2], 1.f);
        atomicAdd(&pos3_s[2*c2],   pos2_s[2*t]);
        atomicAdd(&pos3_s[2*c2+1], pos2_s[2*t+1]);
    }
    __syncthreads();

    // ---- P6: finalize pool-2 positions ----
    if (t < 16){
        float c = cnt2_s[t];
        float invc = 1.f / fmaxf(c, 1.f);
        pos3_s[2*t]   *= invc;
        pos3_s[2*t+1] *= invc;
        d_cnt2[g*16 + t] = c;
        d_pos3[(g*16 + t)*2]     = pos3_s[2*t];
        d_pos3[(g*16 + t)*2 + 1] = pos3_s[2*t+1];
    }
    __syncthreads();

    // ---- P7: m2 partial + build level-3 buckets; write level-2 buckets ----
    {
        float mx = 0.f;
        for (int i = t; i < 64*64; i += 512){
            int r = i >> 6, s = i & 63;
            if (s < bcnt_s[r]){
                int c = bkt_s[i];
                float dx = pos2_s[2*c]   - pos2_s[2*r];
                float dy = pos2_s[2*c+1] - pos2_s[2*r+1];
                mx = fmaxf(mx, fmaxf(fabsf(dx), fabsf(dy)));
                int r3 = cell2_s[r], c3 = cell2_s[c];
                if (r3 != c3){
                    int key = r3*16 + c3;
                    unsigned bit = 1u << (key & 31);
                    unsigned old = atomicOr(&bm3_s[key >> 5], bit);
                    if (!(old & bit)){
                        int sl = atomicAdd(&bcnt3_s[r3], 1);
                        bkt3_s[r3*16 + sl] = (unsigned char)c3;
                    }
                }
            }
        }
        warpMaxAtomic(mx, &d_m[1]);
    }
    if (t < 256) ((uint4*)(d_bkt2 + (size_t)g*4096))[t] = ((uint4*)bkt_s)[t];
    __syncthreads();

    // ---- P8: m3 partial; write level-3 buckets ----
    if (t < 256){
        float mx = 0.f;
        int r = t >> 4, s = t & 15;
        if (s < bcnt3_s[r]){
            int c = bkt3_s[t];
            float dx = pos3_s[2*c]   - pos3_s[2*r];
            float dy = pos3_s[2*c+1] - pos3_s[2*r+1];
            mx = fmaxf(fabsf(dx), fabsf(dy));
        }
        warpMaxAtomic(mx, &d_m[2]);
    }
    if (t < 16){
        d_bcnt3[g*16 + t] = bcnt3_s[t];
        ((uint4*)(d_bkt3 + g*256))[t] = ((uint4*)bkt3_s)[t];
    }
}

// acc2: bin-based, register accumulation, no SMEM accumulator.
// 256 threads, 8 warps, one warp per row. Corner contributions counting-sorted
// into 25 k-bins; per k: reg += w * xs[cl] (LDS+FFMA only), one STG per k.
__global__ void __launch_bounds__(256) k_acc2(){
    __shared__ float xs[64*F1];          // 8 KB
    __shared__ uint2 ent[8][256];        // 16 KB (w, cl) per corner contribution
    __shared__ int   bcur[8][32];        // bin counters -> cursors
    __shared__ int   bstart[8][26];
    int b = blockIdx.x;                  // 2048 = BG*8
    int g = b >> 3, oct = b & 7;
    int t = threadIdx.x, w = t >> 5, lane = t & 31;
    for (int i = t; i < 64*F1/4; i += 256) ((float4*)xs)[i] = ((const float4*)(d_x2 + g*64*F1))[i];
    if (lane < 25) bcur[w][lane] = 0;
    __syncthreads();

    int r = g*64 + oct*8 + w;
    int cnt = d_bcnt2[r];
    float inv = 1.f / (2.f * d_m[1] + 1e-12f);
    float prx = d_pos2[2*r], pry = d_pos2[2*r+1];

    // lane-parallel: weights + bin counts (<=2 edges per lane)
    float4 wv[2]; int kbv[2], clv[2]; int ne = 0;
    for (int e = lane; e < cnt; e += 32){
        int cl = d_bkt2[r*64 + e];
        int c = g*64 + cl;
        float psx = (d_pos2[2*c]   - prx) * inv + 0.5f;
        float psy = (d_pos2[2*c+1] - pry) * inv + 0.5f;
        int ix, iy; float fx, fy;
        spline_corners(psx, psy, ix, iy, fx, fy);
        int kb = ix*5 + iy;
        wv[ne] = make_float4((1.f-fx)*(1.f-fy), (1.f-fx)*fy, fx*(1.f-fy), fx*fy);
        kbv[ne] = kb; clv[ne] = cl; ne++;
        atomicAdd(&bcur[w][kb  ], 1);
        atomicAdd(&bcur[w][kb+1], 1);
        atomicAdd(&bcur[w][kb+5], 1);
        atomicAdd(&bcur[w][kb+6], 1);
    }
    __syncwarp();

    // exclusive scan over 25 bins (shfl inclusive scan)
    int bc = (lane < 25) ? bcur[w][lane] : 0;
    int v = bc;
    #pragma unroll
    for (int o = 1; o < 32; o <<= 1){
        int u = __shfl_up_sync(0xffffffffu, v, o);
        if (lane >= o) v += u;
    }
    int excl = v - bc;
    if (lane < 25){ bstart[w][lane] = excl; bcur[w][lane] = excl; }
    if (lane == 24) bstart[w][25] = v;
    __syncwarp();

    // scatter corner contributions
    for (int i = 0; i < ne; i++){
        int kb = kbv[i]; unsigned cl = (unsigned)clv[i];
        int p;
        p = atomicAdd(&bcur[w][kb  ], 1); ent[w][p] = make_uint2(__float_as_uint(wv[i].x), cl);
        p = atomicAdd(&bcur[w][kb+1], 1); ent[w][p] = make_uint2(__float_as_uint(wv[i].y), cl);
        p = atomicAdd(&bcur[w][kb+5], 1); ent[w][p] = make_uint2(__float_as_uint(wv[i].z), cl);
        p = atomicAdd(&bcur[w][kb+6], 1); ent[w][p] = make_uint2(__float_as_uint(wv[i].w), cl);
    }
    __syncwarp();

    // per-k register accumulation, direct global write
    float invd = 1.f / fmaxf((float)cnt, 1.f);
    size_t rowbase = (size_t)r * (KK*F1);
    int js = bstart[w][0];
    #pragma unroll 5
    for (int k = 0; k < KK; k++){
        int je = bstart[w][k+1];
        float acc = 0.f;
        for (int j = js; j < je; j++){
            uint2 E = ent[w][j];
            acc += __uint_as_float(E.x) * xs[E.y*F1 + lane];
        }
        d_acc2[rowbase + k*F1 + lane] = acc * invd;
        js = je;
    }
}

// ---------------- 256-thread f32x2 GEMM: OUT = elu(A@W + XIN@ROOT + BIAS) ----------------
template<int BM, int TMH, int KDIM, int FIN, int NOUT, bool POOL>
__device__ __forceinline__ void gemm_body(
    const float* __restrict__ A, const float* __restrict__ W,
    const float* __restrict__ XIN, const float* __restrict__ ROOT,
    const float* __restrict__ BIAS, float* __restrict__ OUT)
{
    const int BK = 16, TM = 2*TMH;
    const int A4 = BM*BK/4;
    __shared__ float As[BK][BM + 4];
    __shared__ float Bs[BK][64];
    int bm = blockIdx.x * BM;
    int bn = blockIdx.y * 64;
    int t  = threadIdx.x;            // 256
    int tx = t & 15, ty = t >> 4;
    unsigned long long acc[TMH][4];
    #pragma unroll
    for (int p=0;p<TMH;p++)
        #pragma unroll
        for (int j=0;j<4;j++) acc[p][j]=0ull;

    const int KTOT = KDIM + FIN;
    for (int kk = 0; kk < KTOT; kk += BK){
        bool ext = (kk >= KDIM);
        const float* srcA = ext ? XIN : A;
        const float* srcB = ext ? ROOT : W;
        int ld   = ext ? FIN : KDIM;
        int kofs = ext ? (kk - KDIM) : kk;
        #pragma unroll
        for (int w = 0; w < (A4 + 255)/256; w++){
            int fidx = t + w*256;
            if ((A4 & 255) == 0 || fidx < A4){
                int idx = fidx * 4;
                int m = idx >> 4, k4 = idx & 15;
                float4 v = *(const float4*)&srcA[(size_t)(bm+m)*ld + kofs + k4];
                As[k4+0][m]=v.x; As[k4+1][m]=v.y; As[k4+2][m]=v.z; As[k4+3][m]=v.w;
            }
        }
        {
            int k = t >> 4, n4 = (t & 15) * 4;
            *(float4*)&Bs[k][n4] = *(const float4*)&srcB[(size_t)(kofs+k)*NOUT + bn + n4];
        }
        __syncthreads();
        #pragma unroll
        for (int kb = 0; kb < BK; kb++){
            unsigned long long a[TMH];
            #pragma unroll
            for (int p=0;p<TMH;p++)
                a[p] = *(const unsigned long long*)&As[kb][ty*TM + 2*p];
            float4 b4 = *(const float4*)&Bs[kb][tx*4];
            unsigned long long b0=splat2(b4.x), b1=splat2(b4.y),
                               b2=splat2(b4.z), b3=splat2(b4.w);
            #pragma unroll
            for (int p=0;p<TMH;p++){
                ffma2(acc[p][0], a[p], b0);
                ffma2(acc[p][1], a[p], b1);
                ffma2(acc[p][2], a[p], b2);
                ffma2(acc[p][3], a[p], b3);
            }
        }
        __syncthreads();
    }
    #pragma unroll
    for (int p = 0; p < TMH; p++){
        int m0 = bm + ty*TM + 2*p;
        int ob = bn + tx*4;
        if (POOL){
            #pragma unroll
            for (int half = 0; half < 2; half++){
                int m = m0 + half;
                if (d_cnt1[m] <= 0.f) continue;
                int cl = clu2_of(m);
                #pragma unroll
                for (int j = 0; j < 4; j++){
                    float v = half ? f2hi(acc[p][j]) : f2lo(acc[p][j]);
                    atomicMax(&d_x3u[cl*F2 + ob + j], fenc(eluf(v + BIAS[ob + j])));
                }
            }
        } else {
            float b0 = BIAS[ob], b1 = BIAS[ob+1], b2 = BIAS[ob+2], b3 = BIAS[ob+3];
            float4 o0 = make_float4(eluf(f2lo(acc[p][0])+b0), eluf(f2lo(acc[p][1])+b1),
                                    eluf(f2lo(acc[p][2])+b2), eluf(f2lo(acc[p][3])+b3));
            float4 o1 = make_float4(eluf(f2hi(acc[p][0])+b0), eluf(f2hi(acc[p][1])+b1),
                                    eluf(f2hi(acc[p][2])+b2), eluf(f2hi(acc[p][3])+b3));
            *(float4*)&OUT[(size_t)m0*NOUT + ob]     = o0;
            *(float4*)&OUT[(size_t)(m0+1)*NOUT + ob] = o1;
        }
    }
}

__global__ void k_gemm2pool(const float* __restrict__ W, const float* __restrict__ ROOT,
                            const float* __restrict__ BIAS){
    gemm_body<64, 2, KK*F1, F1, F2, true>(d_acc2, W, d_x2, ROOT, BIAS, nullptr);
}
__global__ void k_gemm3(const float* __restrict__ W, const float* __restrict__ ROOT,
                        const float* __restrict__ BIAS){
    gemm_body<32, 1, KK*F2, F2, F3, false>(d_acc3, W, d_x3f, ROOT, BIAS, d_h3);
}

// decode x3u -> x3f (zero empty clusters) + reset x3u to sentinel for next replay
__global__ void k_fin_x3(){
    int t = blockIdx.x*blockDim.x + threadIdx.x;
    if (t >= NC2*F2) return;
    unsigned u = d_x3u[t];
    d_x3u[t] = 0u;
    float v = 0.f;
    if (d_cnt2[t / F2] > 0.f && u != 0u) v = fdec(u);
    d_x3f[t] = v;
}

// acc3 in SMEM; 8 warps/block, warp per row; pre-divided by deg
__global__ void k_acc3(){
    __shared__ float  acc_s[8*KK*F2];    // 51.2 KB
    __shared__ float  xs[16*F2];         // 4 KB
    __shared__ float4 ew_s[8][16];       // 2 KB
    __shared__ int    em_s[8][16];       // 0.5 KB
    int b = blockIdx.x;                  // 512 = BG*2
    int g = b >> 1, half = b & 1;
    int t = threadIdx.x, w = t >> 5, lane = t & 31;
    float4 z4 = make_float4(0,0,0,0);
    for (int i = t; i < 8*KK*F2/4; i += 256) ((float4*)acc_s)[i] = z4;
    for (int i = t; i < 16*F2/4;   i += 256) ((float4*)xs)[i] = ((const float4*)(d_x3f + g*16*F2))[i];
    __syncthreads();

    int r = g*16 + half*8 + w;
    int cnt = d_bcnt3[r];
    float inv = 1.f / (2.f * d_m[2] + 1e-12f);
    float prx = d_pos3[2*r], pry = d_pos3[2*r+1];

    if (lane < cnt){
        int cl = d_bkt3[r*16 + lane];
        int c = g*16 + cl;
        float psx = (d_pos3[2*c]   - prx) * inv + 0.5f;
        float psy = (d_pos3[2*c+1] - pry) * inv + 0.5f;
        int ix, iy; float fx, fy;
        spline_corners(psx, psy, ix, iy, fx, fy);
        int kb = ix*5 + iy;
        ew_s[w][lane] = make_float4((1.f-fx)*(1.f-fy), (1.f-fx)*fy, fx*(1.f-fy), fx*fy);
        em_s[w][lane] = cl | (kb << 8);
    }
    __syncwarp();

    float* accr = &acc_s[w*KK*F2];
    for (int e = 0; e < cnt; e++){
        float4 wv = ew_s[w][e];
        int meta = em_s[w][e];
        int cl = meta & 255, kb = meta >> 8;
        float xv0 = xs[cl*F2 + lane];
        float xv1 = xs[cl*F2 + lane + 32];
        accr[(kb  )*F2 + lane]      += wv.x * xv0;
        accr[(kb  )*F2 + lane + 32] += wv.x * xv1;
        accr[(kb+1)*F2 + lane]      += wv.y * xv0;
        accr[(kb+1)*F2 + lane + 32] += wv.y * xv1;
        accr[(kb+5)*F2 + lane]      += wv.z * xv0;
        accr[(kb+5)*F2 + lane + 32] += wv.z * xv1;
        accr[(kb+6)*F2 + lane]      += wv.w * xv0;
        accr[(kb+6)*F2 + lane + 32] += wv.w * xv1;
    }
    __syncwarp();
    float invd = 1.f / fmaxf((float)cnt, 1.f);
    size_t rowbase = (size_t)r * (KK*F2);
    #pragma unroll
    for (int k = 0; k < KK; k++){
        d_acc3[rowbase + k*F2 + lane]      = accr[k*F2 + lane]      * invd;
        d_acc3[rowbase + k*F2 + lane + 32] = accr[k*F2 + lane + 32] * invd;
    }
}

// ---------------- readout (+ reset d_m for next replay) ----------------
__global__ void k_readout(const float* __restrict__ fcw, const float* __restrict__ fcb,
                          float* __restrict__ out){
    int g = blockIdx.x, t = threadIdx.x;     // 128 threads
    __shared__ float sf[F3];
    __shared__ float slg[10];
    float s = 0.f, cnt = 0.f;
    for (int j = 0; j < 16; j++){
        int n = g*16 + j;
        float nv = d_cnt2[n] > 0.f ? 1.f : 0.f;
        cnt += nv;
        s += nv * d_h3[n*F3 + t];
    }
    sf[t] = s / fmaxf(cnt, 1.f);
    __syncthreads();
    if (t < 10){
        float l = fcb[t];
        for (int i = 0; i < F3; i++) l += sf[i] * fcw[i*10 + t];
        slg[t] = l;
    }
    __syncthreads();
    if (t == 0){
        float mx = slg[0];
        for (int o = 1; o < 10; o++) mx = fmaxf(mx, slg[o]);
        float se = 0.f;
        for (int o = 0; o < 10; o++) se += expf(slg[o] - mx);
        float lse = logf(se) + mx;
        for (int o = 0; o < 10; o++) out[g*10 + o] = slg[o] - lse;
        if (g == 0){ d_m[0] = 0.f; d_m[1] = 0.f; d_m[2] = 0.f; }
    }
}

// ---------------- launch ----------------
extern "C" void kernel_launch(void* const* d_in, const int* in_sizes, int n_in,
                              void* d_out, int out_size){
    const float* x    = (const float*)d_in[0];
    const float* pos  = (const float*)d_in[1];
    const int*   ei   = (const int*)  d_in[2];
    const float* W1   = (const float*)d_in[4];
    const float* r1   = (const float*)d_in[5];
    const float* b1   = (const float*)d_in[6];
    const float* W2   = (const float*)d_in[7];
    const float* r2p  = (const float*)d_in[8];
    const float* b2   = (const float*)d_in[9];
    const float* W3   = (const float*)d_in[10];
    const float* r3p  = (const float*)d_in[11];
    const float* b3   = (const float*)d_in[12];
    const float* fcw  = (const float*)d_in[13];
    const float* fcb  = (const float*)d_in[14];
    float* out = (float*)d_out;
    const int* row = ei;        // targets
    const int* col = ei + EE;   // sources

    const int G1_SMEM = 512*26*4;      // 53248 bytes dynamic
    cudaFuncSetAttribute(k_graph1, cudaFuncAttributeMaxDynamicSharedMemorySize, G1_SMEM);

    k_nbucket   <<<EE/1024, 256>>>((const int4*)row, (const int4*)col);
    k_m1g       <<<BG, 256>>>(pos);
    k_graph1    <<<BG, 512, G1_SMEM>>>(x, pos, W1, r1, b1);
    k_acc2      <<<BG*8, 256>>>();
    k_gemm2pool <<<dim3(NC1/64, 1), 256>>>(W2, r2p, b2);
    k_fin_x3    <<<NC2*F2/256, 256>>>();
    k_acc3      <<<BG*2, 256>>>();
    k_gemm3     <<<dim3(NC2/32, F3/64), 256>>>(W3, r3p, b3);
    k_readout   <<<BG, 128>>>(fcw, fcb, out);
}

// round 14
// speedup vs baseline: 1.0848x; 1.0848x over previous
#include <cuda_runtime.h>
#include <math.h>

// ---------------- problem constants ----------------
#define BG   256
#define NPG  256
#define NN   (BG*NPG)            // 65536 nodes
#define EE   (NN*16)             // 1048576 edges
#define KK   25
#define F1   32
#define F2   64
#define F3   128
#define NC1  (BG*64)             // 16384 pool-1 clusters
#define NC2  (BG*16)             // 4096  pool-2 clusters
#define NBCAP 64                 // max in-edges per node (avg 16)

// ---------------- device scratch ----------------
__device__ float    d_m[4];
__device__ int      d_ncnt1[NN];
__device__ unsigned char d_nbuf[(size_t)NN*NBCAP];   // 4MB: per-node source bytes
__device__ float    d_x2[NC1*F1];
__device__ float    d_cnt1[NC1];
__device__ float    d_pos2[NC1*2];
__device__ int      d_bcnt2[NC1];
__device__ unsigned char d_bkt2[NC1*64];
__device__ int      d_bcnt3[NC2];
__device__ unsigned char d_bkt3[NC2*16];
__device__ float    d_acc2[(size_t)NC1*KK*F1];  // pre-divided by deg
__device__ float    d_x3[NC2*F2];
__device__ float    d_cnt2[NC2];
__device__ float    d_pos3[NC2*2];
__device__ float    d_acc3[(size_t)NC2*KK*F2];  // pre-divided by deg
__device__ float    d_h3[NC2*F3];

// ---------------- helpers ----------------
__device__ __forceinline__ float eluf(float v){ return v > 0.f ? v : expm1f(v); }

__device__ __forceinline__ void atomicMaxF(float* a, float v){
    if (v >= 0.f) atomicMax((int*)a, __float_as_int(v));
    else          atomicMin((unsigned int*)a, __float_as_uint(v));
}

__device__ __forceinline__ void warpMaxAtomic(float mx, float* dst){
    #pragma unroll
    for (int o = 16; o; o >>= 1) mx = fmaxf(mx, __shfl_xor_sync(0xffffffffu, mx, o));
    if ((threadIdx.x & 31) == 0) atomicMax((int*)dst, __float_as_int(mx));
}

__device__ __forceinline__ void spline_corners(float psx, float psy,
                                               int& ix, int& iy, float& fx, float& fy){
    float vx = psx * 4.f, vy = psy * 4.f;
    float fix = fminf(fmaxf(floorf(vx), 0.f), 3.f);
    float fiy = fminf(fmaxf(floorf(vy), 0.f), 3.f);
    fx = vx - fix; fy = vy - fiy;
    ix = (int)fix; iy = (int)fiy;
}

__device__ __forceinline__ int cell1(float px, float py){
    int cx = min(max((int)floorf(px * 0.25f), 0), 7);
    int cy = min(max((int)floorf(py * 0.25f), 0), 7);
    return cx * 8 + cy;
}
__device__ __forceinline__ int clu2_of(int j){
    float px = d_pos2[2*j], py = d_pos2[2*j+1];
    int cx = min(max((int)floorf(px * 0.125f), 0), 3);
    int cy = min(max((int)floorf(py * 0.125f), 0), 3);
    return (j >> 6) * 16 + cx * 4 + cy;
}

// f32x2 packed FMA helpers
__device__ __forceinline__ unsigned long long splat2(float x){
    unsigned long long r;
    asm("mov.b64 %0, {%1, %1};" : "=l"(r) : "f"(x));
    return r;
}
__device__ __forceinline__ void ffma2(unsigned long long& d,
                                      unsigned long long a, unsigned long long b){
    asm("fma.rn.f32x2 %0, %1, %2, %0;" : "+l"(d) : "l"(a), "l"(b));
}
__device__ __forceinline__ float f2lo(unsigned long long u){ return __uint_as_float((unsigned)u); }
__device__ __forceinline__ float f2hi(unsigned long long u){ return __uint_as_float((unsigned)(u>>32)); }

// ---------------- init ----------------
__global__ void k_init(){
    int t = blockIdx.x*blockDim.x + threadIdx.x;     // 65536
    const float NEG = -3.4e38f;
    ((float4*)d_x3)[t] = make_float4(NEG,NEG,NEG,NEG);   // NC2*F2/4 = 65536
    d_ncnt1[t] = 0;
    if (t < 4) d_m[t] = 0.f;
}

// bucket edges by target node (4 edges per thread)
__global__ void k_nbucket(const int4* __restrict__ row4, const int4* __restrict__ col4){
    int i = blockIdx.x*blockDim.x + threadIdx.x;     // EE/4 threads
    int4 r = row4[i], c = col4[i];
    int s0 = atomicAdd(&d_ncnt1[r.x], 1);
    if (s0 < NBCAP) d_nbuf[(size_t)r.x*NBCAP + s0] = (unsigned char)(c.x & 255);
    int s1 = atomicAdd(&d_ncnt1[r.y], 1);
    if (s1 < NBCAP) d_nbuf[(size_t)r.y*NBCAP + s1] = (unsigned char)(c.y & 255);
    int s2 = atomicAdd(&d_ncnt1[r.z], 1);
    if (s2 < NBCAP) d_nbuf[(size_t)r.z*NBCAP + s2] = (unsigned char)(c.z & 255);
    int s3 = atomicAdd(&d_ncnt1[r.w], 1);
    if (s3 < NBCAP) d_nbuf[(size_t)r.w*NBCAP + s3] = (unsigned char)(c.w & 255);
}

// global pseudo max (level 1) from compact per-node edges; block per graph
__global__ void k_m1g(const float* __restrict__ pos){
    __shared__ float2 ps[NPG];
    int g = blockIdx.x, t = threadIdx.x;
    ps[t] = ((const float2*)pos)[g*NPG + t];
    __syncthreads();
    int gn = g*NPG + t;
    int cnt = min(d_ncnt1[gn], NBCAP);
    const unsigned char* nb = d_nbuf + (size_t)gn*NBCAP;
    float2 mp = ps[t];
    float mx = 0.f;
    for (int e = 0; e < cnt; e++){
        float2 pc = ps[nb[e]];
        mx = fmaxf(mx, fmaxf(fabsf(pc.x - mp.x), fabsf(pc.y - mp.y)));
    }
    warpMaxAtomic(mx, &d_m[0]);
}

// ---------------- mega-kernel: layer1 conv+pool + level2/3 graph build (512 thr) ----------------
__global__ void __launch_bounds__(512) k_graph1(
        const float* __restrict__ x, const float* __restrict__ pos,
        const float* __restrict__ W1, const float* __restrict__ r1,
        const float* __restrict__ b1){
    extern __shared__ float acc_dyn[];     // 512*26 floats = 53.2KB
    __shared__ float  x2_s[64*F1];         // 8KB
    __shared__ unsigned char bkt_s[64*64]; // 4KB
    __shared__ float  W1s[KK*F1];          // 3.2KB
    __shared__ float2 ps[NPG];             // 2KB
    __shared__ float  xs_s[NPG];           // 1KB
    __shared__ unsigned char cell_s[NPG];
    __shared__ unsigned bm_s[128];
    __shared__ int    bcnt_s[64];
    __shared__ float  cnt1_s[64];
    __shared__ float  pos2_s[64*2];
    __shared__ unsigned char cell2_s[64];
    __shared__ unsigned bm3_s[8];
    __shared__ int    bcnt3_s[16];
    __shared__ unsigned char bkt3_s[16*16];
    __shared__ float  cnt2_s[16];
    __shared__ float  pos3_s[16*2];
    __shared__ float  r1s[F1], b1s[F1];

    int g = blockIdx.x, t = threadIdx.x;   // 512 threads
    int half = t >> 8;                      // 0/1
    int n = t & 255;                        // node within graph
    int gn = g*NPG + n;

    // ---- P1: loads + zeroing ----
    float2 myp = ((const float2*)pos)[gn];
    if (half == 0){
        ps[n] = myp;
        xs_s[n] = x[gn];
        cell_s[n] = (unsigned char)cell1(myp.x, myp.y);
    }
    for (int i = t; i < KK*F1; i += 512) W1s[i] = W1[i];
    if (t < F1){ r1s[t] = r1[t]; b1s[t] = b1[t]; }
    #pragma unroll
    for (int k = 0; k < 26; k++) acc_dyn[t*26 + k] = 0.f;
    {
        const float NEG = -3.4e38f;
        for (int i = t; i < 64*F1; i += 512) x2_s[i] = NEG;
    }
    if (t < 128) bm_s[t] = 0u;
    if (t < 64){ bcnt_s[t] = 0; cnt1_s[t] = 0.f; pos2_s[2*t] = 0.f; pos2_s[2*t+1] = 0.f; }
    if (t < 16){ bcnt3_s[t] = 0; cnt2_s[t] = 0.f; pos3_s[2*t] = 0.f; pos3_s[2*t+1] = 0.f; }
    if (t < 8) bm3_s[t] = 0u;
    __syncthreads();

    // ---- P2: per-node edge accumulation (split across thread pair) + level-2 dedup ----
    int rawcnt = d_ncnt1[gn];
    int cnt = min(rawcnt, NBCAP);
    const unsigned char* nb = d_nbuf + (size_t)gn*NBCAP;
    float inv1 = 1.f / (2.f * d_m[0] + 1e-12f);
    float* ar = &acc_dyn[t*26];
    int r2cell = cell_s[n];
    for (int e = half; e < cnt; e += 2){
        int c = nb[e];
        float2 pc = ps[c];
        float psx = (pc.x - myp.x) * inv1 + 0.5f;
        float psy = (pc.y - myp.y) * inv1 + 0.5f;
        int ix, iy; float fx, fy;
        spline_corners(psx, psy, ix, iy, fx, fy);
        float xin = xs_s[c];
        int kb = ix*5 + iy;
        float w00 = (1.f-fx)*(1.f-fy), w01 = (1.f-fx)*fy;
        float w10 = fx*(1.f-fy),       w11 = fx*fy;
        ar[kb  ] += w00 * xin;
        ar[kb+1] += w01 * xin;
        ar[kb+5] += w10 * xin;
        ar[kb+6] += w11 * xin;
        int c2 = cell_s[c];
        if (r2cell != c2){
            int key = r2cell*64 + c2;
            unsigned bit = 1u << (key & 31);
            unsigned old = atomicOr(&bm_s[key >> 5], bit);
            if (!(old & bit)){
                int sl = atomicAdd(&bcnt_s[r2cell], 1);
                bkt_s[r2cell*64 + sl] = (unsigned char)c2;
            }
        }
    }
    __syncthreads();
    // merge the two half-accumulators into rows [0,256)
    if (half == 0){
        #pragma unroll
        for (int k = 0; k < 25; k++) ar[k] += acc_dyn[(t+256)*26 + k];
    }
    __syncthreads();

    // ---- P3: node transform (each thread computes 16 of 32 outputs) + pool-1 ----
    {
        float invd = 1.f / fmaxf((float)rawcnt, 1.f);
        float xn = xs_s[n];
        const float* arn = &acc_dyn[n*26];
        int ob = half*16;
        float h[16];
        #pragma unroll
        for (int j = 0; j < 16; j++) h[j] = b1s[ob+j] + xn * r1s[ob+j];
        #pragma unroll
        for (int k = 0; k < KK; k++){
            float a = arn[k] * invd;
            #pragma unroll
            for (int j = 0; j < 16; j++) h[j] += a * W1s[k*F1 + ob + j];
        }
        int cl = r2cell;
        if (half == 0){
            atomicAdd(&cnt1_s[cl], 1.f);
            atomicAdd(&pos2_s[2*cl],   myp.x);
            atomicAdd(&pos2_s[2*cl+1], myp.y);
        }
        #pragma unroll
        for (int j = 0; j < 16; j++)
            atomicMaxF(&x2_s[cl*F1 + ob + j], eluf(h[j]));
    }
    __syncthreads();

    // ---- P4: finalize clusters ----
    if (t < 64){
        float c = cnt1_s[t];
        float invc = 1.f / fmaxf(c, 1.f);
        float px = pos2_s[2*t] * invc, py = pos2_s[2*t+1] * invc;
        pos2_s[2*t] = px; pos2_s[2*t+1] = py;
        int cx = min(max((int)floorf(px * 0.125f), 0), 3);
        int cy = min(max((int)floorf(py * 0.125f), 0), 3);
        cell2_s[t] = (unsigned char)(cx*4 + cy);
        d_cnt1[g*64 + t] = c;
        d_pos2[(g*64 + t)*2]     = px;
        d_pos2[(g*64 + t)*2 + 1] = py;
        d_bcnt2[g*64 + t] = bcnt_s[t];
    }
    __syncthreads();

    // ---- P5: write x2 (zero empty clusters) + pool-2 meta ----
    for (int i = t; i < 64*F1; i += 512){
        int cl = i >> 5;
        d_x2[g*64*F1 + i] = (cnt1_s[cl] > 0.f) ? x2_s[i] : 0.f;
    }
    if (t < 64 && cnt1_s[t] > 0.f){
        int c2 = cell2_s[t];
        atomicAdd(&cnt2_s[c2], 1.f);
        atomicAdd(&pos3_s[2*c2],   pos2_s[2*t]);
        atomicAdd(&pos3_s[2*c2+1], pos2_s[2*t+1]);
    }
    __syncthreads();

    // ---- P6: finalize pool-2 positions ----
    if (t < 16){
        float c = cnt2_s[t];
        float invc = 1.f / fmaxf(c, 1.f);
        pos3_s[2*t]   *= invc;
        pos3_s[2*t+1] *= invc;
        d_cnt2[g*16 + t] = c;
        d_pos3[(g*16 + t)*2]     = pos3_s[2*t];
        d_pos3[(g*16 + t)*2 + 1] = pos3_s[2*t+1];
    }
    __syncthreads();

    // ---- P7: m2 partial + build level-3 buckets; write level-2 buckets ----
    {
        float mx = 0.f;
        for (int i = t; i < 64*64; i += 512){
            int r = i >> 6, s = i & 63;
            if (s < bcnt_s[r]){
                int c = bkt_s[i];
                float dx = pos2_s[2*c]   - pos2_s[2*r];
                float dy = pos2_s[2*c+1] - pos2_s[2*r+1];
                mx = fmaxf(mx, fmaxf(fabsf(dx), fabsf(dy)));
                int r3 = cell2_s[r], c3 = cell2_s[c];
                if (r3 != c3){
                    int key = r3*16 + c3;
                    unsigned bit = 1u << (key & 31);
                    unsigned old = atomicOr(&bm3_s[key >> 5], bit);
                    if (!(old & bit)){
                        int sl = atomicAdd(&bcnt3_s[r3], 1);
                        bkt3_s[r3*16 + sl] = (unsigned char)c3;
                    }
                }
            }
        }
        warpMaxAtomic(mx, &d_m[1]);
    }
    if (t < 256) ((uint4*)(d_bkt2 + (size_t)g*4096))[t] = ((uint4*)bkt_s)[t];
    __syncthreads();

    // ---- P8: m3 partial; write level-3 buckets ----
    if (t < 256){
        float mx = 0.f;
        int r = t >> 4, s = t & 15;
        if (s < bcnt3_s[r]){
            int c = bkt3_s[t];
            float dx = pos3_s[2*c]   - pos3_s[2*r];
            float dy = pos3_s[2*c+1] - pos3_s[2*r+1];
            mx = fmaxf(fabsf(dx), fabsf(dy));
        }
        warpMaxAtomic(mx, &d_m[2]);
    }
    if (t < 16){
        d_bcnt3[g*16 + t] = bcnt3_s[t];
        ((uint4*)(d_bkt3 + g*256))[t] = ((uint4*)bkt3_s)[t];
    }
}

// acc2[r,k,i] in SMEM; 8 warps/block, one warp per row; pre-divided by deg.
// Weights precomputed lane-parallel into SMEM (2 batches of 32 edges/warp).
__global__ void k_acc2(){
    __shared__ float  acc_s[8*KK*F1];    // 25.6 KB
    __shared__ float  xs[64*F1];         // 8 KB
    __shared__ float4 ew_s[8][64];       // 8 KB
    __shared__ int    em_s[8][64];       // 2 KB
    int b = blockIdx.x;                  // 2048 = BG*8
    int g = b >> 3, oct = b & 7;
    int t = threadIdx.x, w = t >> 5, lane = t & 31;
    float4 z4 = make_float4(0,0,0,0);
    for (int i = t; i < 8*KK*F1/4; i += 256) ((float4*)acc_s)[i] = z4;
    for (int i = t; i < 64*F1/4;   i += 256) ((float4*)xs)[i] = ((const float4*)(d_x2 + g*64*F1))[i];
    __syncthreads();

    int r = g*64 + oct*8 + w;
    int cnt = d_bcnt2[r];
    float inv = 1.f / (2.f * d_m[1] + 1e-12f);
    float prx = d_pos2[2*r], pry = d_pos2[2*r+1];

    // lane-parallel weight precompute
    for (int e = lane; e < cnt; e += 32){
        int cl = d_bkt2[r*64 + e];
        int c = g*64 + cl;
        float psx = (d_pos2[2*c]   - prx) * inv + 0.5f;
        float psy = (d_pos2[2*c+1] - pry) * inv + 0.5f;
        int ix, iy; float fx, fy;
        spline_corners(psx, psy, ix, iy, fx, fy);
        int kb = ix*5 + iy;
        ew_s[w][e] = make_float4((1.f-fx)*(1.f-fy), (1.f-fx)*fy, fx*(1.f-fy), fx*fy);
        em_s[w][e] = cl | (kb << 8);
    }
    __syncwarp();

    float* accr = &acc_s[w*KK*F1];
    for (int e = 0; e < cnt; e++){
        float4 wv = ew_s[w][e];
        int meta = em_s[w][e];
        int cl = meta & 255, kb = meta >> 8;
        float xv = xs[cl*F1 + lane];
        accr[(kb  )*F1 + lane] += wv.x * xv;
        accr[(kb+1)*F1 + lane] += wv.y * xv;
        accr[(kb+5)*F1 + lane] += wv.z * xv;
        accr[(kb+6)*F1 + lane] += wv.w * xv;
    }
    __syncwarp();
    float invd = 1.f / fmaxf((float)cnt, 1.f);
    size_t rowbase = (size_t)r * (KK*F1);
    #pragma unroll
    for (int k = 0; k < KK; k++)
        d_acc2[rowbase + k*F1 + lane] = accr[k*F1 + lane] * invd;
}

// ---------------- 256-thread f32x2 GEMM (BK=32): OUT = elu(A@W + XIN@ROOT + BIAS) ----------------
template<int BM, int TMH, int KDIM, int FIN, int NOUT, bool POOL>
__device__ __forceinline__ void gemm_body(
    const float* __restrict__ A, const float* __restrict__ W,
    const float* __restrict__ XIN, const float* __restrict__ ROOT,
    const float* __restrict__ BIAS, float* __restrict__ OUT)
{
    const int BK = 32, TM = 2*TMH;
    const int A4 = BM*BK/4;          // float4 loads for A tile
    __shared__ float As[BK][BM + 4];
    __shared__ float Bs[BK][64];
    int bm = blockIdx.x * BM;
    int bn = blockIdx.y * 64;
    int t  = threadIdx.x;            // 256
    int tx = t & 15, ty = t >> 4;
    unsigned long long acc[TMH][4];
    #pragma unroll
    for (int p=0;p<TMH;p++)
        #pragma unroll
        for (int j=0;j<4;j++) acc[p][j]=0ull;

    const int KTOT = KDIM + FIN;
    for (int kk = 0; kk < KTOT; kk += BK){
        bool ext = (kk >= KDIM);
        const float* srcA = ext ? XIN : A;
        const float* srcB = ext ? ROOT : W;
        int ld   = ext ? FIN : KDIM;
        int kofs = ext ? (kk - KDIM) : kk;
        #pragma unroll
        for (int w = 0; w < (A4 + 255)/256; w++){
            int fidx = t + w*256;
            if ((A4 & 255) == 0 || fidx < A4){
                int idx = fidx * 4;
                int m = idx >> 5, k4 = idx & 31;
                float4 v = *(const float4*)&srcA[(size_t)(bm+m)*ld + kofs + k4];
                As[k4+0][m]=v.x; As[k4+1][m]=v.y; As[k4+2][m]=v.z; As[k4+3][m]=v.w;
            }
        }
        #pragma unroll
        for (int w = 0; w < 2; w++){
            int fidx = t + w*256;
            int k = fidx >> 4, n4 = (fidx & 15) * 4;
            *(float4*)&Bs[k][n4] = *(const float4*)&srcB[(size_t)(kofs+k)*NOUT + bn + n4];
        }
        __syncthreads();
        #pragma unroll
        for (int kb = 0; kb < BK; kb++){
            unsigned long long a[TMH];
            #pragma unroll
            for (int p=0;p<TMH;p++)
                a[p] = *(const unsigned long long*)&As[kb][ty*TM + 2*p];
            float4 b4 = *(const float4*)&Bs[kb][tx*4];
            unsigned long long b0=splat2(b4.x), b1=splat2(b4.y),
                               b2=splat2(b4.z), b3=splat2(b4.w);
            #pragma unroll
            for (int p=0;p<TMH;p++){
                ffma2(acc[p][0], a[p], b0);
                ffma2(acc[p][1], a[p], b1);
                ffma2(acc[p][2], a[p], b2);
                ffma2(acc[p][3], a[p], b3);
            }
        }
        __syncthreads();
    }
    #pragma unroll
    for (int p = 0; p < TMH; p++){
        int m0 = bm + ty*TM + 2*p;
        int ob = bn + tx*4;
        if (POOL){
            #pragma unroll
            for (int half = 0; half < 2; half++){
                int m = m0 + half;
                if (d_cnt1[m] <= 0.f) continue;
                int cl = clu2_of(m);
                #pragma unroll
                for (int j = 0; j < 4; j++){
                    float v = half ? f2hi(acc[p][j]) : f2lo(acc[p][j]);
                    atomicMaxF(&d_x3[cl*F2 + ob + j], eluf(v + BIAS[ob + j]));
                }
            }
        } else {
            float b0 = BIAS[ob], b1 = BIAS[ob+1], b2 = BIAS[ob+2], b3 = BIAS[ob+3];
            float4 o0 = make_float4(eluf(f2lo(acc[p][0])+b0), eluf(f2lo(acc[p][1])+b1),
                                    eluf(f2lo(acc[p][2])+b2), eluf(f2lo(acc[p][3])+b3));
            float4 o1 = make_float4(eluf(f2hi(acc[p][0])+b0), eluf(f2hi(acc[p][1])+b1),
                                    eluf(f2hi(acc[p][2])+b2), eluf(f2hi(acc[p][3])+b3));
            *(float4*)&OUT[(size_t)m0*NOUT + ob]     = o0;
            *(float4*)&OUT[(size_t)(m0+1)*NOUT + ob] = o1;
        }
    }
}

__global__ void k_gemm2pool(const float* __restrict__ W, const float* __restrict__ ROOT,
                            const float* __restrict__ BIAS){
    gemm_body<64, 2, KK*F1, F1, F2, true>(d_acc2, W, d_x2, ROOT, BIAS, d_x3);
}
__global__ void k_gemm3(const float* __restrict__ W, const float* __restrict__ ROOT,
                        const float* __restrict__ BIAS){
    gemm_body<32, 1, KK*F2, F2, F3, false>(d_acc3, W, d_x3, ROOT, BIAS, d_h3);
}

// x3 zero-fix for empty clusters (before acc3/gemm3 consume x3)
__global__ void k_fin_x3(){
    int t = blockIdx.x*blockDim.x + threadIdx.x;
    if (t >= NC2*F2) return;
    if (d_cnt2[t / F2] <= 0.f) d_x3[t] = 0.f;
}

// acc3 in SMEM; 8 warps/block, warp per row; pre-divided by deg.
// Weights precomputed lane-parallel (<=16 edges/row: one batch).
__global__ void k_acc3(){
    __shared__ float  acc_s[8*KK*F2];    // 51.2 KB
    __shared__ float  xs[16*F2];         // 4 KB
    __shared__ float4 ew_s[8][16];       // 2 KB
    __shared__ int    em_s[8][16];       // 0.5 KB
    int b = blockIdx.x;                  // 512 = BG*2
    int g = b >> 1, half = b & 1;
    int t = threadIdx.x, w = t >> 5, lane = t & 31;
    float4 z4 = make_float4(0,0,0,0);
    for (int i = t; i < 8*KK*F2/4; i += 256) ((float4*)acc_s)[i] = z4;
    for (int i = t; i < 16*F2/4;   i += 256) ((float4*)xs)[i] = ((const float4*)(d_x3 + g*16*F2))[i];
    __syncthreads();

    int r = g*16 + half*8 + w;
    int cnt = d_bcnt3[r];
    float inv = 1.f / (2.f * d_m[2] + 1e-12f);
    float prx = d_pos3[2*r], pry = d_pos3[2*r+1];

    if (lane < cnt){
        int cl = d_bkt3[r*16 + lane];
        int c = g*16 + cl;
        float psx = (d_pos3[2*c]   - prx) * inv + 0.5f;
        float psy = (d_pos3[2*c+1] - pry) * inv + 0.5f;
        int ix, iy; float fx, fy;
        spline_corners(psx, psy, ix, iy, fx, fy);
        int kb = ix*5 + iy;
        ew_s[w][lane] = make_float4((1.f-fx)*(1.f-fy), (1.f-fx)*fy, fx*(1.f-fy), fx*fy);
        em_s[w][lane] = cl | (kb << 8);
    }
    __syncwarp();

    float* accr = &acc_s[w*KK*F2];
    for (int e = 0; e < cnt; e++){
        float4 wv = ew_s[w][e];
        int meta = em_s[w][e];
        int cl = meta & 255, kb = meta >> 8;
        float xv0 = xs[cl*F2 + lane];
        float xv1 = xs[cl*F2 + lane + 32];
        accr[(kb  )*F2 + lane]      += wv.x * xv0;
        accr[(kb  )*F2 + lane + 32] += wv.x * xv1;
        accr[(kb+1)*F2 + lane]      += wv.y * xv0;
        accr[(kb+1)*F2 + lane + 32] += wv.y * xv1;
        accr[(kb+5)*F2 + lane]      += wv.z * xv0;
        accr[(kb+5)*F2 + lane + 32] += wv.z * xv1;
        accr[(kb+6)*F2 + lane]      += wv.w * xv0;
        accr[(kb+6)*F2 + lane + 32] += wv.w * xv1;
    }
    __syncwarp();
    float invd = 1.f / fmaxf((float)cnt, 1.f);
    size_t rowbase = (size_t)r * (KK*F2);
    #pragma unroll
    for (int k = 0; k < KK; k++){
        d_acc3[rowbase + k*F2 + lane]      = accr[k*F2 + lane]      * invd;
        d_acc3[rowbase + k*F2 + lane + 32] = accr[k*F2 + lane + 32] * invd;
    }
}

// ---------------- readout ----------------
__global__ void k_readout(const float* __restrict__ fcw, const float* __restrict__ fcb,
                          float* __restrict__ out){
    int g = blockIdx.x, t = threadIdx.x;     // 128 threads
    __shared__ float sf[F3];
    __shared__ float slg[10];
    float s = 0.f, cnt = 0.f;
    for (int j = 0; j < 16; j++){
        int n = g*16 + j;
        float nv = d_cnt2[n] > 0.f ? 1.f : 0.f;
        cnt += nv;
        s += nv * d_h3[n*F3 + t];
    }
    sf[t] = s / fmaxf(cnt, 1.f);
    __syncthreads();
    if (t < 10){
        float l = fcb[t];
        for (int i = 0; i < F3; i++) l += sf[i] * fcw[i*10 + t];
        slg[t] = l;
    }
    __syncthreads();
    if (t == 0){
        float mx = slg[0];
        for (int o = 1; o < 10; o++) mx = fmaxf(mx, slg[o]);
        float se = 0.f;
        for (int o = 0; o < 10; o++) se += expf(slg[o] - mx);
        float lse = logf(se) + mx;
        for (int o = 0; o < 10; o++) out[g*10 + o] = slg[o] - lse;
    }
}

// ---------------- launch ----------------
extern "C" void kernel_launch(void* const* d_in, const int* in_sizes, int n_in,
                              void* d_out, int out_size){
    const float* x    = (const float*)d_in[0];
    const float* pos  = (const float*)d_in[1];
    const int*   ei   = (const int*)  d_in[2];
    const float* W1   = (const float*)d_in[4];
    const float* r1   = (const float*)d_in[5];
    const float* b1   = (const float*)d_in[6];
    const float* W2   = (const float*)d_in[7];
    const float* r2p  = (const float*)d_in[8];
    const float* b2   = (const float*)d_in[9];
    const float* W3   = (const float*)d_in[10];
    const float* r3p  = (const float*)d_in[11];
    const float* b3   = (const float*)d_in[12];
    const float* fcw  = (const float*)d_in[13];
    const float* fcb  = (const float*)d_in[14];
    float* out = (float*)d_out;
    const int* row = ei;        // targets
    const int* col = ei + EE;   // sources

    const int G1_SMEM = 512*26*4;   // 53248 bytes dynamic
    cudaFuncSetAttribute(k_graph1, cudaFuncAttributeMaxDynamicSharedMemorySize, G1_SMEM);

    k_init      <<<256, 256>>>();
    k_nbucket   <<<EE/1024, 256>>>((const int4*)row, (const int4*)col);
    k_m1g       <<<BG, 256>>>(pos);
    k_graph1    <<<BG, 512, G1_SMEM>>>(x, pos, W1, r1, b1);
    k_acc2      <<<BG*8, 256>>>();
    k_gemm2pool <<<dim3(NC1/64, 1), 256>>>(W2, r2p, b2);
    k_fin_x3    <<<NC2*F2/256, 256>>>();
    k_acc3      <<<BG*2, 256>>>();
    k_gemm3     <<<dim3(NC2/32, F3/64), 256>>>(W3, r3p, b3);
    k_readout   <<<BG, 128>>>(fcw, fcb, out);
}